// round 15
// baseline (speedup 1.0000x reference)
#include <cuda_runtime.h>
#include <cuda_fp16.h>
#include <cstdint>

// ============================================================
// SKANLinear: y[b,o] = sum_i max(w[o,i] * x_aug[b,i], 0)
//   = 0.5 * ( X Wt + |X| |W|t ) + relu(w[o,256])
// f16 mma.m16n8k16 dual GEMM (fp32 accum).
//  R12: mma dependency-distance fix (normal block then abs block),
//       ldmatrix fragment double-buffering, non-volatile mma.
// ============================================================

#define BM 128
#define BN 128
#define KD 256
#define WST 257
#define KB 64
#define NST 4
#define THREADS 512

// smem byte offsets
#define SM_BIAS 0                   // 128 f32
#define SM_A    1024                // 2 x 16384 (128 rows x 128B, swizzled)
#define SM_B    (1024 + 32768)      // 65536 (128 rows x 512B, swizzled)
#define SMEM_TOTAL (SM_B + 65536)   // 99328

__device__ __forceinline__ uint32_t smem_u32(const void* p) {
    uint32_t a;
    asm("{ .reg .u64 t; cvta.to.shared.u64 t, %1; cvt.u32.u64 %0, t; }" : "=r"(a) : "l"(p));
    return a;
}

__device__ __forceinline__ uint32_t f2h2(float lo, float hi) {
    __half2 h = __floats2half2_rn(lo, hi);
    return *(uint32_t*)&h;
}

__device__ __forceinline__ void ldsm4(uint32_t* r, uint32_t addr) {
    asm volatile("ldmatrix.sync.aligned.m8n8.x4.shared.b16 {%0,%1,%2,%3}, [%4];"
                 : "=r"(r[0]), "=r"(r[1]), "=r"(r[2]), "=r"(r[3]) : "r"(addr));
}

// non-volatile: deps carried by constraints, ptxas free to schedule
__device__ __forceinline__ void mma16816(float* c, const uint32_t* a,
                                         uint32_t b0, uint32_t b1) {
    asm("mma.sync.aligned.m16n8k16.row.col.f32.f16.f16.f32 "
        "{%0,%1,%2,%3}, {%4,%5,%6,%7}, {%8,%9}, {%0,%1,%2,%3};"
        : "+f"(c[0]), "+f"(c[1]), "+f"(c[2]), "+f"(c[3])
        : "r"(a[0]), "r"(a[1]), "r"(a[2]), "r"(a[3]), "r"(b0), "r"(b1));
}

__global__ void __launch_bounds__(THREADS, 1)
skan_f16(const float* __restrict__ x, const float* __restrict__ w,
         float* __restrict__ out) {
    extern __shared__ char sm[];
    const uint32_t smb = smem_u32(sm);
    const int tid = threadIdx.x;
    const int wid = tid >> 5, ln = tid & 31;
    const int warpM = wid & 3, warpN = wid >> 2;      // 4x4 warp grid
    const int bm = blockIdx.x * BM;
    const int bn = blockIdx.y * BN;

    // ---------------- prologue ----------------
    // A stage-0 LDG into regs (DRAM latency first)
    float4 ra[4];
    #pragma unroll
    for (int j = 0; j < 4; j++) {
        int idx = tid + j * THREADS;                  // 0..2047
        int row = idx >> 4, c4 = idx & 15;            // 128 rows x 16 float4
        ra[j] = *(const float4*)&x[(bm + row) * KD + c4 * 4];
    }

    // W block rows [bn, bn+128): contiguous flat 128*257 floats.
    // Coalesced float4 load + divmod scatter into swizzled f16 tile;
    // col 256 (bias) -> relu into SM_BIAS.
    {
        const float* wflat = w + (size_t)bn * WST;
        #pragma unroll
        for (int j = 0; j < 17; j++) {
            int f = tid + j * THREADS;                // float4 index
            if (f < 8224) {
                float4 v = *(const float4*)&wflat[f * 4];
                int e0 = f * 4;
                int n = e0 / 257;
                int c = e0 - n * 257;
                float vv[4] = {v.x, v.y, v.z, v.w};
                #pragma unroll
                for (int u = 0; u < 4; u++) {
                    if (c == 257) { c = 0; n++; }
                    if (c < 256) {
                        uint16_t h = __half_as_ushort(__float2half_rn(vv[u]));
                        uint32_t off = (uint32_t)(c * 2) ^ (uint32_t)((n & 7) << 4);
                        *(uint16_t*)(sm + SM_B + n * 512 + off) = h;
                    } else {
                        *(float*)(sm + SM_BIAS + n * 4) = fmaxf(vv[u], 0.0f);
                    }
                    c++;
                }
            }
        }
    }

    // A stage-0 STS (128B rows, SW128 swizzle)
    #pragma unroll
    for (int j = 0; j < 4; j++) {
        int idx = tid + j * THREADS;
        int row = idx >> 4, c4 = idx & 15;
        uint32_t off = (uint32_t)(c4 * 8) ^ (uint32_t)((row & 7) << 4);
        uint2 pk;
        pk.x = f2h2(ra[j].x, ra[j].y);
        pk.y = f2h2(ra[j].z, ra[j].w);
        *(uint2*)(sm + SM_A + row * 128 + off) = pk;
    }
    __syncthreads();

    // ---------------- per-lane ldmatrix address bases ----------------
    uint32_t baseA[2], m60A[2];
    {
        const int qA = (ln >> 4) * 16;                // byte offset of k-half
        #pragma unroll
        for (int tm = 0; tm < 2; tm++) {
            int rowl = warpM * 32 + tm * 16 + (ln & 15);
            uint32_t mA = (uint32_t)((rowl & 7) << 4);
            baseA[tm] = smb + SM_A + rowl * 128 + ((uint32_t)qA ^ (mA & 16u));
            m60A[tm] = mA & 0x60u;
        }
    }
    uint32_t baseB[2], m60B[2];
    {
        const int noff = (ln & 7) + ((ln >> 4) << 3);
        const int khB = ((ln >> 3) & 1) * 16;
        #pragma unroll
        for (int p = 0; p < 2; p++) {
            int nl = warpN * 32 + p * 16 + noff;
            uint32_t mB = (uint32_t)((nl & 7) << 4);
            baseB[p] = smb + SM_B + nl * 512 + ((uint32_t)khB ^ (mB & 16u));
            m60B[p] = mB & 0x60u;
        }
    }

    float acc[2][4][4];
    #pragma unroll
    for (int tm = 0; tm < 2; tm++)
        #pragma unroll
        for (int tn = 0; tn < 4; tn++)
            #pragma unroll
            for (int r = 0; r < 4; r++) acc[tm][tn][r] = 0.0f;

    // fragment double buffers
    uint32_t af[2][2][4], bf[2][2][4];

    #define LDFRAGS(dst, bufo, sB, kb)                                   \
        ldsm4(af[dst][0], baseA[0] + (bufo) + ((kb) ^ m60A[0]));         \
        ldsm4(af[dst][1], baseA[1] + (bufo) + ((kb) ^ m60A[1]));         \
        ldsm4(bf[dst][0], baseB[0] + (sB) + ((kb) ^ m60B[0]));           \
        ldsm4(bf[dst][1], baseB[1] + (sB) + ((kb) ^ m60B[1]));

    // ---------------- main loop: 4 stages, 1 sync per stage ----------------
    #pragma unroll
    for (int s = 0; s < NST; s++) {
        const uint32_t bufo = (uint32_t)((s & 1) * 16384);
        const uint32_t sB = (uint32_t)(s * 128);

        // prefetch next A stage into regs (DRAM latency under mmas)
        if (s + 1 < NST) {
            #pragma unroll
            for (int j = 0; j < 4; j++) {
                int idx = tid + j * THREADS;
                int row = idx >> 4, c4 = idx & 15;
                ra[j] = *(const float4*)&x[(bm + row) * KD + (s + 1) * KB + c4 * 4];
            }
        }

        // preload fragments for kstep 0
        LDFRAGS(0, bufo, sB, 0u);

        #pragma unroll
        for (int ks = 0; ks < 4; ks++) {
            const int cur = ks & 1;

            // issue next kstep's ldmatrix early (latency hidden under mmas)
            if (ks < 3) {
                const uint32_t kb = (uint32_t)((ks + 1) * 32);
                LDFRAGS(cur ^ 1, bufo, sB, kb);
            }

            // abs fragments in registers
            uint32_t aa[2][4], bb[2][4];
            #pragma unroll
            for (int i = 0; i < 4; i++) {
                aa[0][i] = af[cur][0][i] & 0x7FFF7FFFu;
                aa[1][i] = af[cur][1][i] & 0x7FFF7FFFu;
                bb[0][i] = bf[cur][0][i] & 0x7FFF7FFFu;
                bb[1][i] = bf[cur][1][i] & 0x7FFF7FFFu;
            }

            // 8 independent normal mmas ...
            #pragma unroll
            for (int tm = 0; tm < 2; tm++)
                #pragma unroll
                for (int tn = 0; tn < 4; tn++) {
                    const int p = tn >> 1, h = (tn & 1) * 2;
                    mma16816(acc[tm][tn], af[cur][tm], bf[cur][p][h], bf[cur][p][h + 1]);
                }
            // ... then 8 abs mmas (RAW distance 8 to their partners)
            #pragma unroll
            for (int tm = 0; tm < 2; tm++)
                #pragma unroll
                for (int tn = 0; tn < 4; tn++) {
                    const int p = tn >> 1, h = (tn & 1) * 2;
                    mma16816(acc[tm][tn], aa[tm], bb[p][h], bb[p][h + 1]);
                }
        }

        // stage next A tile
        if (s + 1 < NST) {
            #pragma unroll
            for (int j = 0; j < 4; j++) {
                int idx = tid + j * THREADS;
                int row = idx >> 4, c4 = idx & 15;
                uint32_t off = (uint32_t)(c4 * 8) ^ (uint32_t)((row & 7) << 4);
                uint2 pk;
                pk.x = f2h2(ra[j].x, ra[j].y);
                pk.y = f2h2(ra[j].z, ra[j].w);
                *(uint2*)(sm + SM_A + ((s + 1) & 1) * 16384 + row * 128 + off) = pk;
            }
            __syncthreads();
        }
    }

    // ---------------- epilogue ----------------
    const int lg = ln >> 2, lt = ln & 3;
    #pragma unroll
    for (int tm = 0; tm < 2; tm++) {
        const int row = bm + warpM * 32 + tm * 16 + lg;
        #pragma unroll
        for (int tn = 0; tn < 4; tn++) {
            const int col = warpN * 32 + tn * 8 + 2 * lt;
            float2 bias = *(const float2*)(sm + SM_BIAS + col * 4);
            float2 v0, v1;
            v0.x = 0.5f * acc[tm][tn][0] + bias.x;
            v0.y = 0.5f * acc[tm][tn][1] + bias.y;
            v1.x = 0.5f * acc[tm][tn][2] + bias.x;
            v1.y = 0.5f * acc[tm][tn][3] + bias.y;
            *(float2*)&out[row * 256 + bn + col]       = v0;
            *(float2*)&out[(row + 8) * 256 + bn + col] = v1;
        }
    }
}

extern "C" void kernel_launch(void* const* d_in, const int* in_sizes, int n_in,
                              void* d_out, int out_size) {
    const float* x = (const float*)d_in[0];   // 8192 x 256
    const float* w = (const float*)d_in[1];   // 256 x 257
    float* out = (float*)d_out;               // 8192 x 256

    cudaFuncSetAttribute(skan_f16, cudaFuncAttributeMaxDynamicSharedMemorySize,
                         SMEM_TOTAL);
    dim3 grid(8192 / BM, 256 / BN);           // 64 x 2 = 128 CTAs, one wave
    skan_f16<<<grid, THREADS, SMEM_TOTAL>>>(x, w, out);
}